// round 11
// baseline (speedup 1.0000x reference)
#include <cuda_runtime.h>
#include <math.h>
#include <float.h>

// UCBSampler: rewards[i,j] = probs[i,j] + 0.5*sqrt(log(i+1) / (1 + i*(1 + i*N + j)))
// out[i] = argmax_j rewards[i,j]  (first index on ties), stored as FLOAT32.
//
// Round-11: R9 proved the indices this kernel computes are bit-correct
// (host-verified). R10 proved int64 stores still give rel_err == 1.0 exactly.
// Unifying model: the checker compares 4096 float32 values; every previous
// write format (int32 bits, int64 bits, 0xAA poison) reads as ~0.0f in f32,
// and ||0 - ref||/||ref|| == 1.0 exactly. Fix: store the index as float.

#define NNODES  32000
#define NV4     (NNODES / 4)      // 8000 float4 per row
#define BATCH   4096
#define THREADS 256

__global__ __launch_bounds__(THREADS)
void ucb_argmax_kernel(const float* __restrict__ probs,
                       float* __restrict__ out)
{
    __shared__ float s_v[THREADS / 32];
    __shared__ int   s_i[THREADS / 32];

    const int row = blockIdx.x;
    const int t   = threadIdx.x;

    const float4* gp = reinterpret_cast<const float4*>(probs + (size_t)row * NNODES);

    // per-row constants (reference f32 association: (1 + i*N) then +j)
    const float fi = (float)row;
    const float L  = logf(fi + 1.0f);                     // log(1) = 0 exactly
    const float base_inner = __fadd_rn(1.0f, __fmul_rn(fi, (float)NNODES));

    float bestv = -FLT_MAX;
    int   besti = 0;

    #pragma unroll 4
    for (int f = t; f < NV4; f += THREADS) {
        float4 val = gp[f];
        float pv[4] = {val.x, val.y, val.z, val.w};
        #pragma unroll
        for (int k = 0; k < 4; k++) {
            int   j     = 4 * f + k;
            // exact reference rounding: no FMA contraction, div.rn, sqrt.rn
            float inner = __fadd_rn(base_inner, (float)j);
            float denom = __fadd_rn(1.0f, __fmul_rn(fi, inner));
            float b     = __fmul_rn(0.5f, __fsqrt_rn(__fdiv_rn(L, denom)));
            float r     = __fadd_rn(pv[k], b);
            // strict > keeps first index within a thread (j increasing);
            // cross-thread ties resolved by min-index in the reduction
            if (r > bestv) { bestv = r; besti = j; }
        }
    }

    // warp argmax reduce (max value, min index on ties)
    #pragma unroll
    for (int o = 16; o > 0; o >>= 1) {
        float ov = __shfl_xor_sync(0xffffffffu, bestv, o);
        int   oi = __shfl_xor_sync(0xffffffffu, besti, o);
        if (ov > bestv || (ov == bestv && oi < besti)) { bestv = ov; besti = oi; }
    }
    if ((t & 31) == 0) { s_v[t >> 5] = bestv; s_i[t >> 5] = besti; }
    __syncthreads();

    if (t < 32) {
        const int nw = THREADS / 32;
        float v2 = (t < nw) ? s_v[t] : -FLT_MAX;
        int   i2 = (t < nw) ? s_i[t] : 0;
        #pragma unroll
        for (int o = 16; o > 0; o >>= 1) {
            float ov = __shfl_xor_sync(0xffffffffu, v2, o);
            int   oi = __shfl_xor_sync(0xffffffffu, i2, o);
            if (ov > v2 || (ov == v2 && oi < i2)) { v2 = ov; i2 = oi; }
        }
        if (t == 0) out[row] = (float)i2;   // FLOAT32 store of the index
    }
}

extern "C" void kernel_launch(void* const* d_in, const int* in_sizes, int n_in,
                              void* d_out, int out_size)
{
    const float* probs = (const float*)d_in[0];   // verified: single f32 input
    float*       out   = (float*)d_out;
    (void)in_sizes; (void)n_in; (void)out_size;

    ucb_argmax_kernel<<<BATCH, THREADS>>>(probs, out);
}

// round 12
// speedup vs baseline: 1.3835x; 1.3835x over previous
#include <cuda_runtime.h>
#include <math.h>
#include <float.h>

// UCBSampler: rewards[i,j] = probs[i,j] + 0.5*sqrt(log(i+1) / (1 + i*(1 + i*N + j)))
// out[i] = (float)argmax_j rewards[i,j]  (first index on ties).
//
// Round-12: candidate-filter kernel. Phase 1 streams the row into SMEM while
// computing the plain fmax row max (no transcendentals -> DRAM-bound).
// The bonus is monotone decreasing in j with spread (bmax - bmin); only
// elements with p >= rowmax - spread - slack can win. Phase 2 rescans SMEM
// (4-wide max + 1 compare per float4) and evaluates the exact
// reference-rounded reward (non-contracted f32, div.rn/sqrt.rn) for the
// ~10-25 candidates per row. Output float32 (verified in R11).

#define NNODES  32000
#define NV4     (NNODES / 4)      // 8000 float4 per row
#define BATCH   4096
#define THREADS 1024
#define ITERS   8                 // ceil(8000 / 1024)

__global__ __launch_bounds__(THREADS, 1)
void ucb_filter_kernel(const float* __restrict__ probs,
                       float* __restrict__ out)
{
    extern __shared__ float srow[];          // NNODES floats (128000 B)
    __shared__ float s_v[32];
    __shared__ int   s_i[32];
    __shared__ float s_m1;

    const int row = blockIdx.x;
    const int t   = threadIdx.x;

    const float4* gp = reinterpret_cast<const float4*>(probs + (size_t)row * NNODES);
    float4*       sp = reinterpret_cast<float4*>(srow);

    // ---- Phase 1: stream row into SMEM, plain max of p ----
    float lmax = -FLT_MAX;
    #pragma unroll
    for (int v = 0; v < ITERS; v++) {
        int f = t + v * THREADS;
        if (f < NV4) {
            float4 val = gp[f];
            sp[f] = val;
            lmax = fmaxf(lmax, fmaxf(fmaxf(val.x, val.y), fmaxf(val.z, val.w)));
        }
    }

    // block max reduce
    #pragma unroll
    for (int o = 16; o > 0; o >>= 1)
        lmax = fmaxf(lmax, __shfl_xor_sync(0xffffffffu, lmax, o));
    if ((t & 31) == 0) s_v[t >> 5] = lmax;
    __syncthreads();
    if (t < 32) {
        float m = s_v[t];
        #pragma unroll
        for (int o = 16; o > 0; o >>= 1)
            m = fmaxf(m, __shfl_xor_sync(0xffffffffu, m, o));
        if (t == 0) s_m1 = m;
    }
    __syncthreads();
    const float M1 = s_m1;
    __syncthreads();               // s_v reads complete; safe to reuse

    // ---- Per-row constants (reference f32 association) ----
    const float fi = (float)row;
    const float L  = logf(fi + 1.0f);                       // log(1)=0 exact
    const float base_inner = __fadd_rn(1.0f, __fmul_rn(fi, (float)NNODES));

    // bonus spread bound for the candidate filter (inflated; not bit-critical)
    const float d0 = __fadd_rn(1.0f, __fmul_rn(fi, base_inner));
    const float dN = __fadd_rn(1.0f,
                      __fmul_rn(fi, __fadd_rn(base_inner, (float)(NNODES - 1))));
    const float bmax = 0.5f * sqrtf(L / d0);
    const float bmin = 0.5f * sqrtf(L / dN);
    const float thresh = M1 - (bmax - bmin) * 1.01f - 1e-6f;

    // ---- Phase 2: rescan SMEM, exact reward only for candidates ----
    float bestv = -FLT_MAX;
    int   besti = 0;
    #pragma unroll
    for (int v = 0; v < ITERS; v++) {
        int f = t + v * THREADS;
        if (f < NV4) {
            float4 val = sp[f];
            float m4 = fmaxf(fmaxf(val.x, val.y), fmaxf(val.z, val.w));
            if (m4 >= thresh) {                       // rare path
                float pv[4] = {val.x, val.y, val.z, val.w};
                #pragma unroll
                for (int k = 0; k < 4; k++) {
                    if (pv[k] >= thresh) {
                        int   j     = 4 * f + k;
                        // exact reference rounding (verified in R9/R11)
                        float inner = __fadd_rn(base_inner, (float)j);
                        float denom = __fadd_rn(1.0f, __fmul_rn(fi, inner));
                        float b = __fmul_rn(0.5f, __fsqrt_rn(__fdiv_rn(L, denom)));
                        float r = __fadd_rn(pv[k], b);
                        if (r > bestv || (r == bestv && j < besti)) {
                            bestv = r; besti = j;
                        }
                    }
                }
            }
        }
    }

    // ---- Phase 3: block (val, idx) argmax reduce, tie -> min idx ----
    #pragma unroll
    for (int o = 16; o > 0; o >>= 1) {
        float ov = __shfl_xor_sync(0xffffffffu, bestv, o);
        int   oi = __shfl_xor_sync(0xffffffffu, besti, o);
        if (ov > bestv || (ov == bestv && oi < besti)) { bestv = ov; besti = oi; }
    }
    if ((t & 31) == 0) { s_v[t >> 5] = bestv; s_i[t >> 5] = besti; }
    __syncthreads();
    if (t < 32) {
        float v2 = s_v[t];
        int   i2 = s_i[t];
        #pragma unroll
        for (int o = 16; o > 0; o >>= 1) {
            float ov = __shfl_xor_sync(0xffffffffu, v2, o);
            int   oi = __shfl_xor_sync(0xffffffffu, i2, o);
            if (ov > v2 || (ov == v2 && oi < i2)) { v2 = ov; i2 = oi; }
        }
        if (t == 0) out[row] = (float)i2;
    }
}

extern "C" void kernel_launch(void* const* d_in, const int* in_sizes, int n_in,
                              void* d_out, int out_size)
{
    const float* probs = (const float*)d_in[0];
    float*       out   = (float*)d_out;
    (void)in_sizes; (void)n_in; (void)out_size;

    const int smem_bytes = NNODES * (int)sizeof(float);   // 128000
    cudaFuncSetAttribute(ucb_filter_kernel,
                         cudaFuncAttributeMaxDynamicSharedMemorySize,
                         smem_bytes);

    ucb_filter_kernel<<<BATCH, THREADS, smem_bytes>>>(probs, out);
}

// round 13
// speedup vs baseline: 1.4674x; 1.0606x over previous
#include <cuda_runtime.h>
#include <math.h>
#include <float.h>

// UCBSampler: rewards[i,j] = probs[i,j] + 0.5*sqrt(log(i+1) / (1 + i*(1 + i*N + j)))
// out[i] = (float)argmax_j rewards[i,j]  (first index on ties).
//
// Round-13: quarter-row CTAs for phase overlap. R12 (whole-row, 128KB smem)
// ran 1 CTA/SM, serializing the load phase and the SMEM-rescan phase ->
// DRAM 60.5%. Splitting rows into 4 quarters (32KB smem, 256 thr) gives
// ~5 CTAs/SM so phases overlap across CTAs. Each quarter-CTA outputs the
// EXACT best (reward, index) of its quarter (same verified reference-rounded
// math + spread filter, bound computed over the quarter's j-range); a tiny
// combine kernel merges 4 partials per row with first-index tie-break.

#define NNODES  32000
#define QELEMS  8000              // elements per quarter
#define QV4     (QELEMS / 4)      // 2000 float4
#define BATCH   4096
#define NQ      4
#define THREADS 256

__device__ float g_pv[BATCH * NQ];   // partial best reward per quarter
__device__ int   g_pi[BATCH * NQ];   // partial best index  per quarter

__global__ __launch_bounds__(THREADS)
void ucb_quarter_kernel(const float* __restrict__ probs)
{
    extern __shared__ float sq[];        // QELEMS floats (32000 B)
    __shared__ float s_v[THREADS / 32];
    __shared__ int   s_i[THREADS / 32];
    __shared__ float s_m1;

    const int cta = blockIdx.x;
    const int row = cta >> 2;
    const int q   = cta & 3;
    const int t   = threadIdx.x;
    const int j0  = q * QELEMS;

    const float4* gp = reinterpret_cast<const float4*>(
        probs + (size_t)row * NNODES + j0);
    float4* sp = reinterpret_cast<float4*>(sq);

    // ---- Phase 1: stream quarter into SMEM, plain max ----
    float lmax = -FLT_MAX;
    #pragma unroll
    for (int v = 0; v < 8; v++) {
        int f = t + v * THREADS;
        if (f < QV4) {
            float4 val = gp[f];
            sp[f] = val;
            lmax = fmaxf(lmax, fmaxf(fmaxf(val.x, val.y), fmaxf(val.z, val.w)));
        }
    }

    // block max reduce
    #pragma unroll
    for (int o = 16; o > 0; o >>= 1)
        lmax = fmaxf(lmax, __shfl_xor_sync(0xffffffffu, lmax, o));
    if ((t & 31) == 0) s_v[t >> 5] = lmax;
    __syncthreads();
    if (t < 32) {
        float m = (t < THREADS / 32) ? s_v[t] : -FLT_MAX;
        #pragma unroll
        for (int o = 4; o > 0; o >>= 1)
            m = fmaxf(m, __shfl_xor_sync(0xffffffffu, m, o));
        if (t == 0) s_m1 = m;
    }
    __syncthreads();
    const float M1 = s_m1;
    __syncthreads();              // s_v reads done; reuse below

    // ---- per-row constants (reference f32 association) ----
    const float fi = (float)row;
    const float L  = logf(fi + 1.0f);                    // log(1)=0 exact
    const float base_inner = __fadd_rn(1.0f, __fmul_rn(fi, (float)NNODES));

    // spread bound over THIS quarter's j-range (inflated; not bit-critical)
    const float dA = __fadd_rn(1.0f,
                      __fmul_rn(fi, __fadd_rn(base_inner, (float)j0)));
    const float dB = __fadd_rn(1.0f,
                      __fmul_rn(fi, __fadd_rn(base_inner, (float)(j0 + QELEMS - 1))));
    const float bA = 0.5f * sqrtf(L / dA);
    const float bB = 0.5f * sqrtf(L / dB);
    const float thresh = M1 - (bA - bB) * 1.01f - 1e-6f;

    // ---- Phase 2: rescan SMEM, exact reward only for candidates ----
    float bestv = -FLT_MAX;
    int   besti = j0;
    #pragma unroll
    for (int v = 0; v < 8; v++) {
        int f = t + v * THREADS;
        if (f < QV4) {
            float4 val = sp[f];
            float m4 = fmaxf(fmaxf(val.x, val.y), fmaxf(val.z, val.w));
            if (m4 >= thresh) {                          // rare path
                float pv[4] = {val.x, val.y, val.z, val.w};
                #pragma unroll
                for (int k = 0; k < 4; k++) {
                    if (pv[k] >= thresh) {
                        int   j     = j0 + 4 * f + k;
                        // exact reference rounding (verified R9/R11/R12)
                        float inner = __fadd_rn(base_inner, (float)j);
                        float denom = __fadd_rn(1.0f, __fmul_rn(fi, inner));
                        float b = __fmul_rn(0.5f, __fsqrt_rn(__fdiv_rn(L, denom)));
                        float r = __fadd_rn(pv[k], b);
                        if (r > bestv || (r == bestv && j < besti)) {
                            bestv = r; besti = j;
                        }
                    }
                }
            }
        }
    }

    // ---- Phase 3: block argmax reduce (tie -> min idx), write partial ----
    #pragma unroll
    for (int o = 16; o > 0; o >>= 1) {
        float ov = __shfl_xor_sync(0xffffffffu, bestv, o);
        int   oi = __shfl_xor_sync(0xffffffffu, besti, o);
        if (ov > bestv || (ov == bestv && oi < besti)) { bestv = ov; besti = oi; }
    }
    if ((t & 31) == 0) { s_v[t >> 5] = bestv; s_i[t >> 5] = besti; }
    __syncthreads();
    if (t < 32) {
        float v2 = (t < THREADS / 32) ? s_v[t] : -FLT_MAX;
        int   i2 = (t < THREADS / 32) ? s_i[t] : 0x7fffffff;
        #pragma unroll
        for (int o = 4; o > 0; o >>= 1) {
            float ov = __shfl_xor_sync(0xffffffffu, v2, o);
            int   oi = __shfl_xor_sync(0xffffffffu, i2, o);
            if (ov > v2 || (ov == v2 && oi < i2)) { v2 = ov; i2 = oi; }
        }
        if (t == 0) { g_pv[cta] = v2; g_pi[cta] = i2; }
    }
}

__global__ __launch_bounds__(256)
void ucb_combine_kernel(float* __restrict__ out)
{
    int row = blockIdx.x * 256 + threadIdx.x;
    if (row >= BATCH) return;
    int base = row * NQ;
    float bv = g_pv[base];
    int   bi = g_pi[base];
    #pragma unroll
    for (int k = 1; k < NQ; k++) {
        float v = g_pv[base + k];
        int   i = g_pi[base + k];
        // quarters are index-ordered; strict > keeps the first index on ties
        if (v > bv) { bv = v; bi = i; }
    }
    out[row] = (float)bi;
}

extern "C" void kernel_launch(void* const* d_in, const int* in_sizes, int n_in,
                              void* d_out, int out_size)
{
    const float* probs = (const float*)d_in[0];
    float*       out   = (float*)d_out;
    (void)in_sizes; (void)n_in; (void)out_size;

    const int smem_bytes = QELEMS * (int)sizeof(float);   // 32000 (< 48KB, no opt-in)
    ucb_quarter_kernel<<<BATCH * NQ, THREADS, smem_bytes>>>(probs);
    ucb_combine_kernel<<<(BATCH + 255) / 256, 256>>>(out);
}